// round 1
// baseline (speedup 1.0000x reference)
#include <cuda_runtime.h>
#include <math.h>

// ---------------------------------------------------------------------------
// Net_6983616823390: binarized MLP
//   L1: h1 = relu( x @ sign(W1)^T * mean|W1| + b1 )            x fp32 [8192,3072]
//   L2-4: h = relu( (mean(h_prev)*mean|W|) * (step(h_prev) @ sign(W)^T) + b )
//   L5: out = h4 @ W5^T + b5
// Round 0: precision-faithful fp32 SIMT baseline. Deterministic fixed-order
// reductions (fp64 accumulate) for all scalar scales.
// ---------------------------------------------------------------------------

#define B_ROWS 8192
#define HDIM   2000
#define DIN    3072

#define BM 128
#define BN 128
#define BK 16
#define TM 8
#define TN 8

#define RED_BLOCKS 512
#define RED_THREADS 256

// scalar scales: [0..3] = mean|W1..W4|, [4..6] = mean(h1..h3)
__device__ float  d_scales[8];
__device__ double d_partials[8][RED_BLOCKS];

// ping-pong activation buffers (65.5 MB each)
__device__ float g_bufA[(size_t)B_ROWS * HDIM];
__device__ float g_bufB[(size_t)B_ROWS * HDIM];

// ---------------------------------------------------------------------------
// Deterministic two-stage mean(|.|) reduction
// ---------------------------------------------------------------------------
__global__ void __launch_bounds__(RED_THREADS)
reduce_abs_partial(const float* __restrict__ src, long n, int slot) {
    double s = 0.0;
    long stride = (long)gridDim.x * blockDim.x;
    for (long i = (long)blockIdx.x * blockDim.x + threadIdx.x; i < n; i += stride)
        s += (double)fabsf(src[i]);
    __shared__ double sm[RED_THREADS];
    sm[threadIdx.x] = s;
    __syncthreads();
    for (int o = RED_THREADS / 2; o > 0; o >>= 1) {
        if (threadIdx.x < o) sm[threadIdx.x] += sm[threadIdx.x + o];
        __syncthreads();
    }
    if (threadIdx.x == 0) d_partials[slot][blockIdx.x] = sm[0];
}

__global__ void __launch_bounds__(RED_BLOCKS)
reduce_finalize(int slot, double invn) {
    __shared__ double sm[RED_BLOCKS];
    sm[threadIdx.x] = d_partials[slot][threadIdx.x];
    __syncthreads();
    for (int o = RED_BLOCKS / 2; o > 0; o >>= 1) {
        if (threadIdx.x < o) sm[threadIdx.x] += sm[threadIdx.x + o];
        __syncthreads();
    }
    if (threadIdx.x == 0) d_scales[slot] = (float)(sm[0] * invn);
}

// ---------------------------------------------------------------------------
// Fused binarized GEMM + scale + bias + ReLU.
//   C[m][n] = relu( alpha * sum_k f(A[m][k]) * sign(W[n][k]) + bias[n] )
//   f = identity (stepA=0, layer 1) or step (stepA=1, layers 2-4)
//   alpha = d_scales[sW] * (sA >= 0 ? d_scales[sA] : 1)
// M is a multiple of BM; K a multiple of BK; N guarded.
// ---------------------------------------------------------------------------
__device__ __forceinline__ float sgnf(float v) {
    return (v > 0.f) ? 1.f : ((v < 0.f) ? -1.f : 0.f);
}

__global__ void __launch_bounds__(256)
gemm_bin(const float* __restrict__ A, const float* __restrict__ W,
         const float* __restrict__ bias, float* __restrict__ C,
         int N, int K, int sA, int sW, int stepA)
{
    __shared__ float As[BK][BM];
    __shared__ float Bs[BK][BN];

    const int tid  = threadIdx.x;
    const int brow = blockIdx.y * BM;   // M offset
    const int bcol = blockIdx.x * BN;   // N offset
    const int trow = tid >> 4;          // 0..15
    const int tcol = tid & 15;          // 0..15

    float acc[TM][TN];
#pragma unroll
    for (int i = 0; i < TM; i++)
#pragma unroll
        for (int j = 0; j < TN; j++) acc[i][j] = 0.f;

    for (int k0 = 0; k0 < K; k0 += BK) {
        // ---- load A tile (128x16 fp32) as float4, apply step() if needed ----
#pragma unroll
        for (int it = 0; it < 2; it++) {
            int idx4 = tid + it * 256;          // 0..511
            int r  = idx4 >> 2;                  // 0..127
            int c4 = (idx4 & 3) * 4;             // 0,4,8,12
            const float4 v = *(const float4*)&A[(long)(brow + r) * K + k0 + c4];
            float vx = v.x, vy = v.y, vz = v.z, vw = v.w;
            if (stepA) {
                vx = (vx > 0.f) ? 1.f : 0.f;
                vy = (vy > 0.f) ? 1.f : 0.f;
                vz = (vz > 0.f) ? 1.f : 0.f;
                vw = (vw > 0.f) ? 1.f : 0.f;
            }
            As[c4 + 0][r] = vx;
            As[c4 + 1][r] = vy;
            As[c4 + 2][r] = vz;
            As[c4 + 3][r] = vw;
        }
        // ---- load W tile (128x16 fp32), apply sign() ----
#pragma unroll
        for (int it = 0; it < 2; it++) {
            int idx4 = tid + it * 256;
            int r  = idx4 >> 2;
            int c4 = (idx4 & 3) * 4;
            int gr = bcol + r;
            float4 v = make_float4(0.f, 0.f, 0.f, 0.f);
            if (gr < N) v = *(const float4*)&W[(long)gr * K + k0 + c4];
            Bs[c4 + 0][r] = sgnf(v.x);
            Bs[c4 + 1][r] = sgnf(v.y);
            Bs[c4 + 2][r] = sgnf(v.z);
            Bs[c4 + 3][r] = sgnf(v.w);
        }
        __syncthreads();

#pragma unroll
        for (int k = 0; k < BK; k++) {
            float ra[TM], rb[TN];
#pragma unroll
            for (int i = 0; i < TM; i++) ra[i] = As[k][trow * TM + i];
#pragma unroll
            for (int j = 0; j < TN; j++) rb[j] = Bs[k][tcol * TN + j];
#pragma unroll
            for (int i = 0; i < TM; i++)
#pragma unroll
                for (int j = 0; j < TN; j++)
                    acc[i][j] = fmaf(ra[i], rb[j], acc[i][j]);
        }
        __syncthreads();
    }

    const float alpha = ((sA >= 0) ? d_scales[sA] : 1.f) * d_scales[sW];
#pragma unroll
    for (int i = 0; i < TM; i++) {
        int gr = brow + trow * TM + i;
#pragma unroll
        for (int j = 0; j < TN; j++) {
            int gc = bcol + tcol * TN + j;
            if (gc < N) {
                float v = fmaf(alpha, acc[i][j], bias[gc]);
                C[(long)gr * HDIM + gc] = fmaxf(v, 0.f);
            }
        }
    }
}

// ---------------------------------------------------------------------------
// Final layer: out[m][c] = sum_k h4[m][k] * W5[c][k] + b5[c]   (N = 10)
// One warp per output row.
// ---------------------------------------------------------------------------
__global__ void __launch_bounds__(256)
fc_out(const float* __restrict__ H4, const float* __restrict__ W5,
       const float* __restrict__ b5, float* __restrict__ out)
{
    int warp = (blockIdx.x * blockDim.x + threadIdx.x) >> 5;
    int lane = threadIdx.x & 31;
    if (warp >= B_ROWS) return;
    const float* h = H4 + (long)warp * HDIM;
    float acc[10];
#pragma unroll
    for (int j = 0; j < 10; j++) acc[j] = 0.f;
    for (int k = lane; k < HDIM; k += 32) {
        float hv = h[k];
#pragma unroll
        for (int j = 0; j < 10; j++)
            acc[j] = fmaf(hv, W5[j * HDIM + k], acc[j]);
    }
#pragma unroll
    for (int j = 0; j < 10; j++) {
#pragma unroll
        for (int o = 16; o > 0; o >>= 1)
            acc[j] += __shfl_down_sync(0xffffffffu, acc[j], o);
    }
    if (lane == 0) {
#pragma unroll
        for (int j = 0; j < 10; j++)
            out[(long)warp * 10 + j] = acc[j] + b5[j];
    }
}

// ---------------------------------------------------------------------------
extern "C" void kernel_launch(void* const* d_in, const int* in_sizes, int n_in,
                              void* d_out, int out_size)
{
    const float* x  = (const float*)d_in[0];
    const float* W1 = (const float*)d_in[1];
    const float* b1 = (const float*)d_in[2];
    const float* W2 = (const float*)d_in[3];
    const float* b2 = (const float*)d_in[4];
    const float* W3 = (const float*)d_in[5];
    const float* b3 = (const float*)d_in[6];
    const float* W4 = (const float*)d_in[7];
    const float* b4 = (const float*)d_in[8];
    const float* W5 = (const float*)d_in[9];
    const float* b5 = (const float*)d_in[10];
    float* out = (float*)d_out;

    float* bufA = nullptr;
    float* bufB = nullptr;
    cudaGetSymbolAddress((void**)&bufA, g_bufA);
    cudaGetSymbolAddress((void**)&bufB, g_bufB);

    const long nW1 = (long)HDIM * DIN;     // 6,144,000
    const long nW  = (long)HDIM * HDIM;    // 4,000,000
    const long nH  = (long)B_ROWS * HDIM;  // 16,384,000

    dim3 gemm_grid((HDIM + BN - 1) / BN, B_ROWS / BM);  // (16, 64)

    // weight scales
    reduce_abs_partial<<<RED_BLOCKS, RED_THREADS>>>(W1, nW1, 0);
    reduce_finalize<<<1, RED_BLOCKS>>>(0, 1.0 / (double)nW1);
    reduce_abs_partial<<<RED_BLOCKS, RED_THREADS>>>(W2, nW, 1);
    reduce_finalize<<<1, RED_BLOCKS>>>(1, 1.0 / (double)nW);
    reduce_abs_partial<<<RED_BLOCKS, RED_THREADS>>>(W3, nW, 2);
    reduce_finalize<<<1, RED_BLOCKS>>>(2, 1.0 / (double)nW);
    reduce_abs_partial<<<RED_BLOCKS, RED_THREADS>>>(W4, nW, 3);
    reduce_finalize<<<1, RED_BLOCKS>>>(3, 1.0 / (double)nW);

    // layer 1: x (fp32, identity) @ sign(W1)^T, alpha = s_W1
    gemm_bin<<<gemm_grid, 256>>>(x, W1, b1, bufA, HDIM, DIN, -1, 0, 0);
    reduce_abs_partial<<<RED_BLOCKS, RED_THREADS>>>(bufA, nH, 4);
    reduce_finalize<<<1, RED_BLOCKS>>>(4, 1.0 / (double)nH);

    // layer 2: step(h1) @ sign(W2)^T, alpha = s_h1 * s_W2
    gemm_bin<<<gemm_grid, 256>>>(bufA, W2, b2, bufB, HDIM, HDIM, 4, 1, 1);
    reduce_abs_partial<<<RED_BLOCKS, RED_THREADS>>>(bufB, nH, 5);
    reduce_finalize<<<1, RED_BLOCKS>>>(5, 1.0 / (double)nH);

    // layer 3
    gemm_bin<<<gemm_grid, 256>>>(bufB, W3, b3, bufA, HDIM, HDIM, 5, 2, 1);
    reduce_abs_partial<<<RED_BLOCKS, RED_THREADS>>>(bufA, nH, 6);
    reduce_finalize<<<1, RED_BLOCKS>>>(6, 1.0 / (double)nH);

    // layer 4
    gemm_bin<<<gemm_grid, 256>>>(bufA, W4, b4, bufB, HDIM, HDIM, 6, 3, 1);

    // layer 5 (fp32, no binarization, no relu)
    fc_out<<<(B_ROWS * 32) / 256, 256>>>(bufB, W5, b5, out);

    (void)in_sizes; (void)n_in; (void)out_size;
}

// round 3
// speedup vs baseline: 4.1607x; 4.1607x over previous
#include <cuda_runtime.h>
#include <cuda_bf16.h>
#include <cstdint>
#include <math.h>

// ===========================================================================
// Net_6983616823390 — binarized MLP, mma.sync (HMMA) path for sm_103
//  (tcgen05 unavailable: harness PTX targets compute_103, not compute_103a)
//  L1 : h1 = relu( (x_hi|x_lo) @ sign(W1)^T * s_W1 + b1 )   K=6144 bf16
//  L2-4: h = relu( s_h*s_W * (step(h) @ sign(W)^T) + b )     exact bf16 int GEMM
//  L5 : out = h4 @ W5^T + b5                                 fp32 SIMT
// ===========================================================================

#define B_ROWS 8192
#define HDIM   2000
#define HPAD   2048
#define DIN    3072
#define K1PAD  6144

#define RED_BLOCKS 512
#define RED_THREADS 256
#define GPARTS 1024

#define TILE_M 128
#define TILE_N 128
#define TILE_K 32
#define APAD   40      // row stride (bf16 elems) for conflict-free ldmatrix

__device__ float  d_scales[8];
__device__ double d_partials[8][GPARTS];

__device__ __align__(16) __nv_bfloat16 g_xs  [(size_t)B_ROWS * K1PAD];
__device__ __align__(16) __nv_bfloat16 g_sw1 [(size_t)HPAD * K1PAD];
__device__ __align__(16) __nv_bfloat16 g_sw2 [(size_t)HPAD * HPAD];
__device__ __align__(16) __nv_bfloat16 g_sw3 [(size_t)HPAD * HPAD];
__device__ __align__(16) __nv_bfloat16 g_sw4 [(size_t)HPAD * HPAD];
__device__ __align__(16) __nv_bfloat16 g_stepA[(size_t)B_ROWS * HPAD];
__device__ __align__(16) __nv_bfloat16 g_stepB[(size_t)B_ROWS * HPAD];
__device__ __align__(16) float g_h4[(size_t)B_ROWS * HDIM];

__device__ __forceinline__ uint32_t smem_u32(const void* p) {
    uint32_t a;
    asm("{ .reg .u64 t; cvta.to.shared.u64 t, %1; cvt.u32.u64 %0, t; }" : "=r"(a) : "l"(p));
    return a;
}
__device__ __forceinline__ void ldm_x4(uint32_t* r, uint32_t addr) {
    asm volatile("ldmatrix.sync.aligned.m8n8.x4.shared.b16 {%0,%1,%2,%3}, [%4];"
        : "=r"(r[0]), "=r"(r[1]), "=r"(r[2]), "=r"(r[3]) : "r"(addr));
}
__device__ __forceinline__ void mma16816(float* c, const uint32_t* a,
                                         uint32_t b0, uint32_t b1) {
    asm volatile(
        "mma.sync.aligned.m16n8k16.row.col.f32.bf16.bf16.f32 "
        "{%0,%1,%2,%3}, {%4,%5,%6,%7}, {%8,%9}, {%0,%1,%2,%3};"
        : "+f"(c[0]), "+f"(c[1]), "+f"(c[2]), "+f"(c[3])
        : "r"(a[0]), "r"(a[1]), "r"(a[2]), "r"(a[3]), "r"(b0), "r"(b1));
}

// ===========================================================================
// Deterministic reductions
// ===========================================================================
__global__ void __launch_bounds__(RED_THREADS)
reduce_abs_partial(const float* __restrict__ src, long n, int slot) {
    double s = 0.0;
    long stride = (long)gridDim.x * blockDim.x;
    for (long i = (long)blockIdx.x * blockDim.x + threadIdx.x; i < n; i += stride)
        s += (double)fabsf(src[i]);
    __shared__ double sm[RED_THREADS];
    sm[threadIdx.x] = s; __syncthreads();
    for (int o = RED_THREADS / 2; o > 0; o >>= 1) {
        if (threadIdx.x < o) sm[threadIdx.x] += sm[threadIdx.x + o];
        __syncthreads();
    }
    if (threadIdx.x == 0) d_partials[slot][blockIdx.x] = sm[0];
}
__global__ void __launch_bounds__(512)
reduce_finalize(int slot, double invn, int nparts) {
    __shared__ double sm[512];
    int t = threadIdx.x;
    double v = (t < nparts) ? d_partials[slot][t] : 0.0;
    if (t + 512 < nparts) v += d_partials[slot][t + 512];
    sm[t] = v; __syncthreads();
    for (int o = 256; o > 0; o >>= 1) {
        if (t < o) sm[t] += sm[t + o];
        __syncthreads();
    }
    if (t == 0) d_scales[slot] = (float)(sm[0] * invn);
}

// ===========================================================================
// Conversions
// ===========================================================================
__global__ void __launch_bounds__(256)
k_split_x(const float* __restrict__ x) {
    long gid = (long)blockIdx.x * blockDim.x + threadIdx.x;
    long n4 = (long)B_ROWS * DIN / 4;
    if (gid >= n4) return;
    int m = (int)(gid / (DIN / 4));
    int c = (int)(gid % (DIN / 4)) * 4;
    const float4 v = *(const float4*)&x[(long)m * DIN + c];
    float vv[4] = {v.x, v.y, v.z, v.w};
    __nv_bfloat16 hi[4], lo[4];
#pragma unroll
    for (int i = 0; i < 4; i++) {
        hi[i] = __float2bfloat16(vv[i]);
        lo[i] = __float2bfloat16(vv[i] - __bfloat162float(hi[i]));
    }
    *(uint2*)&g_xs[(long)m * K1PAD + c]       = *(uint2*)hi;
    *(uint2*)&g_xs[(long)m * K1PAD + DIN + c] = *(uint2*)lo;
}
__device__ __forceinline__ uint32_t sgn_pair(float a, float b) {
    uint32_t lo = (a > 0.f) ? 0x3F80u : ((a < 0.f) ? 0xBF80u : 0u);
    uint32_t hi = (b > 0.f) ? 0x3F80u : ((b < 0.f) ? 0xBF80u : 0u);
    return lo | (hi << 16);
}
__global__ void __launch_bounds__(256)
k_sign_w1(const float* __restrict__ W1) {
    long gid = (long)blockIdx.x * blockDim.x + threadIdx.x;
    long n2 = (long)HPAD * K1PAD / 2;
    if (gid >= n2) return;
    int r = (int)(gid / (K1PAD / 2));
    int c = (int)(gid % (K1PAD / 2)) * 2;
    uint32_t w = 0;
    if (r < HDIM) {
        int sc = (c < DIN) ? c : (c - DIN);
        w = sgn_pair(W1[(long)r * DIN + sc], W1[(long)r * DIN + sc + 1]);
    }
    *(uint32_t*)&g_sw1[(long)r * K1PAD + c] = w;
}
__global__ void __launch_bounds__(256)
k_sign_w(const float* __restrict__ W, __nv_bfloat16* __restrict__ dst) {
    long gid = (long)blockIdx.x * blockDim.x + threadIdx.x;
    long n2 = (long)HPAD * HPAD / 2;
    if (gid >= n2) return;
    int r = (int)(gid / (HPAD / 2));
    int c = (int)(gid % (HPAD / 2)) * 2;
    uint32_t w = 0;
    if (r < HDIM && c < HDIM)
        w = sgn_pair(W[(long)r * HDIM + c], W[(long)r * HDIM + c + 1]);
    *(uint32_t*)&dst[(long)r * HPAD + c] = w;
}

// ===========================================================================
// HMMA GEMM: C[128,128] = A[M,K] @ W[N,K]^T, fused epilogue.
//   8 warps: (wm 0-1) x (wn 0-3); each warp 64x32 via 4x4 m16n8k16 frags.
// ===========================================================================
__global__ void __launch_bounds__(256, 2)
gemm_mma(const __nv_bfloat16* __restrict__ A, int lda,
         const __nv_bfloat16* __restrict__ Bw, int ldb,
         const float* __restrict__ bias, int K, int Nvalid,
         __nv_bfloat16* __restrict__ stepOut, float* __restrict__ h4Out,
         int sA, int sW, int slot)
{
    __shared__ __align__(16) __nv_bfloat16 As[2][TILE_M][APAD];
    __shared__ __align__(16) __nv_bfloat16 Bs[2][TILE_N][APAD];
    __shared__ double smr[256];

    const int tid  = threadIdx.x;
    const int wid  = tid >> 5;
    const int lane = tid & 31;
    const int wm   = wid >> 2;        // 0..1
    const int wn   = wid & 3;         // 0..3
    const int brow = blockIdx.y * TILE_M;
    const int bcol = blockIdx.x * TILE_N;
    const int NC   = K >> 5;

    const int lrow = tid >> 2;        // 0..63
    const int lseg = tid & 3;         // 0..3
    const __nv_bfloat16* Abase = A  + (size_t)(brow + lrow) * lda + lseg * 8;
    const __nv_bfloat16* Bbase = Bw + (size_t)(bcol + lrow) * ldb + lseg * 8;
    const size_t Astep64 = (size_t)64 * lda;
    const size_t Bstep64 = (size_t)64 * ldb;

    const uint32_t as0 = smem_u32(&As[0][0][0]);
    const uint32_t bs0 = smem_u32(&Bs[0][0][0]);
    const uint32_t BUFB = TILE_M * APAD * 2;   // bytes per buffer
    const uint32_t st_off = lrow * (APAD * 2) + lseg * 16;

    // ldmatrix lane address offsets (bytes), within a buffer
    const int aj = lane & 7, asel = lane >> 3;
    const uint32_t a_off = (uint32_t)((wm * 64 + aj + (asel & 1) * 8) * (APAD * 2)
                                      + (asel >> 1) * 16);
    const uint32_t b_off = (uint32_t)((wn * 32 + aj + (asel >> 1) * 8) * (APAD * 2)
                                      + (asel & 1) * 16);

    float acc[4][4][4];
#pragma unroll
    for (int i = 0; i < 4; i++)
#pragma unroll
        for (int j = 0; j < 4; j++)
#pragma unroll
            for (int q = 0; q < 4; q++) acc[i][j][q] = 0.f;

    // preload stage 0
    {
        uint4 a0 = *(const uint4*)Abase;
        uint4 a1 = *(const uint4*)(Abase + Astep64);
        uint4 b0 = *(const uint4*)Bbase;
        uint4 b1 = *(const uint4*)(Bbase + Bstep64);
        *(uint4*)((char*)As + st_off) = a0;
        *(uint4*)((char*)As + st_off + 64 * APAD * 2) = a1;
        *(uint4*)((char*)Bs + st_off) = b0;
        *(uint4*)((char*)Bs + st_off + 64 * APAD * 2) = b1;
    }
    __syncthreads();

    for (int it = 0; it < NC; it++) {
        const int buf = it & 1;
        uint4 pa0, pa1, pb0, pb1;
        const bool more = (it + 1 < NC);
        if (more) {
            const __nv_bfloat16* An = Abase + (size_t)(it + 1) * 32;
            const __nv_bfloat16* Bn = Bbase + (size_t)(it + 1) * 32;
            pa0 = *(const uint4*)An;
            pa1 = *(const uint4*)(An + Astep64);
            pb0 = *(const uint4*)Bn;
            pb1 = *(const uint4*)(Bn + Bstep64);
        }

        const uint32_t ab = as0 + buf * BUFB;
        const uint32_t bb = bs0 + buf * BUFB;
#pragma unroll
        for (int ks = 0; ks < 2; ks++) {
            uint32_t bfr[2][4];
#pragma unroll
            for (int p = 0; p < 2; p++)
                ldm_x4(bfr[p], bb + b_off + p * 16 * (APAD * 2) + ks * 32);
#pragma unroll
            for (int mf = 0; mf < 4; mf++) {
                uint32_t afr[4];
                ldm_x4(afr, ab + a_off + mf * 16 * (APAD * 2) + ks * 32);
#pragma unroll
                for (int nf = 0; nf < 4; nf++)
                    mma16816(acc[mf][nf], afr,
                             bfr[nf >> 1][(nf & 1) * 2], bfr[nf >> 1][(nf & 1) * 2 + 1]);
            }
        }

        if (more) {
            char* ad = (char*)As + (buf ^ 1) * BUFB + st_off;
            char* bd = (char*)Bs + (buf ^ 1) * BUFB + st_off;
            *(uint4*)ad = pa0;
            *(uint4*)(ad + 64 * APAD * 2) = pa1;
            *(uint4*)bd = pb0;
            *(uint4*)(bd + 64 * APAD * 2) = pb1;
        }
        __syncthreads();
    }

    // ---------------- epilogue ----------------
    const float alpha = d_scales[sW] * ((sA >= 0) ? d_scales[sA] : 1.f);
    double mysum = 0.0;
#pragma unroll
    for (int mf = 0; mf < 4; mf++) {
        const int m0 = brow + wm * 64 + mf * 16 + (lane >> 2);
#pragma unroll
        for (int nf = 0; nf < 4; nf++) {
            const int n = bcol + wn * 32 + nf * 8 + 2 * (lane & 3);
            const bool v0 = (n < Nvalid), v1 = (n + 1 < Nvalid);
            const float bv0 = v0 ? bias[n] : 0.f;
            const float bv1 = v1 ? bias[n + 1] : 0.f;
            float p00 = fmaf(alpha, acc[mf][nf][0], bv0);
            float p01 = fmaf(alpha, acc[mf][nf][1], bv1);
            float p10 = fmaf(alpha, acc[mf][nf][2], bv0);
            float p11 = fmaf(alpha, acc[mf][nf][3], bv1);
            float h00 = (v0 && p00 > 0.f) ? p00 : 0.f;
            float h01 = (v1 && p01 > 0.f) ? p01 : 0.f;
            float h10 = (v0 && p10 > 0.f) ? p10 : 0.f;
            float h11 = (v1 && p11 > 0.f) ? p11 : 0.f;
            mysum += (double)h00 + (double)h01 + (double)h10 + (double)h11;
            if (stepOut) {
                uint32_t s0 = (h00 > 0.f ? 0x3F80u : 0u) | ((h01 > 0.f ? 0x3F80u : 0u) << 16);
                uint32_t s1 = (h10 > 0.f ? 0x3F80u : 0u) | ((h11 > 0.f ? 0x3F80u : 0u) << 16);
                *(uint32_t*)&stepOut[(size_t)m0 * HPAD + n] = s0;
                *(uint32_t*)&stepOut[(size_t)(m0 + 8) * HPAD + n] = s1;
            }
            if (h4Out && v0) {
                *(float2*)&h4Out[(size_t)m0 * HDIM + n] = make_float2(h00, h01);
                *(float2*)&h4Out[(size_t)(m0 + 8) * HDIM + n] = make_float2(h10, h11);
            }
        }
    }

    smr[tid] = mysum;
    __syncthreads();
    for (int o = 128; o > 0; o >>= 1) {
        if (tid < o) smr[tid] += smr[tid + o];
        __syncthreads();
    }
    if (tid == 0 && slot >= 0)
        d_partials[slot][blockIdx.y * gridDim.x + blockIdx.x] = smr[0];
}

// ===========================================================================
// Final fp32 layer (N=10)
// ===========================================================================
__global__ void __launch_bounds__(256)
fc_out(const float* __restrict__ H4, const float* __restrict__ W5,
       const float* __restrict__ b5, float* __restrict__ out)
{
    int warp = (blockIdx.x * blockDim.x + threadIdx.x) >> 5;
    int lane = threadIdx.x & 31;
    if (warp >= B_ROWS) return;
    const float* h = H4 + (long)warp * HDIM;
    float acc[10];
#pragma unroll
    for (int j = 0; j < 10; j++) acc[j] = 0.f;
    for (int k = lane; k < HDIM; k += 32) {
        float hv = h[k];
#pragma unroll
        for (int j = 0; j < 10; j++)
            acc[j] = fmaf(hv, W5[j * HDIM + k], acc[j]);
    }
#pragma unroll
    for (int j = 0; j < 10; j++)
#pragma unroll
        for (int o = 16; o > 0; o >>= 1)
            acc[j] += __shfl_down_sync(0xffffffffu, acc[j], o);
    if (lane == 0)
#pragma unroll
        for (int j = 0; j < 10; j++)
            out[(long)warp * 10 + j] = acc[j] + b5[j];
}

// ===========================================================================
extern "C" void kernel_launch(void* const* d_in, const int* in_sizes, int n_in,
                              void* d_out, int out_size)
{
    const float* x  = (const float*)d_in[0];
    const float* W1 = (const float*)d_in[1];
    const float* b1 = (const float*)d_in[2];
    const float* W2 = (const float*)d_in[3];
    const float* b2 = (const float*)d_in[4];
    const float* W3 = (const float*)d_in[5];
    const float* b3 = (const float*)d_in[6];
    const float* W4 = (const float*)d_in[7];
    const float* b4 = (const float*)d_in[8];
    const float* W5 = (const float*)d_in[9];
    const float* b5 = (const float*)d_in[10];
    float* out = (float*)d_out;

    __nv_bfloat16 *xs, *sw1, *sw2, *sw3, *sw4, *stA, *stB;
    float* h4;
    cudaGetSymbolAddress((void**)&xs,  g_xs);
    cudaGetSymbolAddress((void**)&sw1, g_sw1);
    cudaGetSymbolAddress((void**)&sw2, g_sw2);
    cudaGetSymbolAddress((void**)&sw3, g_sw3);
    cudaGetSymbolAddress((void**)&sw4, g_sw4);
    cudaGetSymbolAddress((void**)&stA, g_stepA);
    cudaGetSymbolAddress((void**)&stB, g_stepB);
    cudaGetSymbolAddress((void**)&h4,  g_h4);

    const long nW1 = (long)HDIM * DIN;
    const long nW  = (long)HDIM * HDIM;
    const double invH = 1.0 / ((double)B_ROWS * HDIM);

    reduce_abs_partial<<<RED_BLOCKS, RED_THREADS>>>(W1, nW1, 0);
    reduce_finalize<<<1, 512>>>(0, 1.0 / (double)nW1, RED_BLOCKS);
    reduce_abs_partial<<<RED_BLOCKS, RED_THREADS>>>(W2, nW, 1);
    reduce_finalize<<<1, 512>>>(1, 1.0 / (double)nW, RED_BLOCKS);
    reduce_abs_partial<<<RED_BLOCKS, RED_THREADS>>>(W3, nW, 2);
    reduce_finalize<<<1, 512>>>(2, 1.0 / (double)nW, RED_BLOCKS);
    reduce_abs_partial<<<RED_BLOCKS, RED_THREADS>>>(W4, nW, 3);
    reduce_finalize<<<1, 512>>>(3, 1.0 / (double)nW, RED_BLOCKS);

    k_split_x<<<(int)(((long)B_ROWS * DIN / 4 + 255) / 256), 256>>>(x);
    k_sign_w1<<<(int)(((long)HPAD * K1PAD / 2 + 255) / 256), 256>>>(W1);
    k_sign_w<<<(int)(((long)HPAD * HPAD / 2 + 255) / 256), 256>>>(W2, sw2);
    k_sign_w<<<(int)(((long)HPAD * HPAD / 2 + 255) / 256), 256>>>(W3, sw3);
    k_sign_w<<<(int)(((long)HPAD * HPAD / 2 + 255) / 256), 256>>>(W4, sw4);

    dim3 grid(HPAD / TILE_N, B_ROWS / TILE_M);   // (16, 64) = 1024 CTAs

    gemm_mma<<<grid, 256>>>(xs, K1PAD, sw1, K1PAD, b1, K1PAD, HDIM,
                            stA, nullptr, -1, 0, 4);
    reduce_finalize<<<1, 512>>>(4, invH, GPARTS);
    gemm_mma<<<grid, 256>>>(stA, HPAD, sw2, HPAD, b2, HPAD, HDIM,
                            stB, nullptr, 4, 1, 5);
    reduce_finalize<<<1, 512>>>(5, invH, GPARTS);
    gemm_mma<<<grid, 256>>>(stB, HPAD, sw3, HPAD, b3, HPAD, HDIM,
                            stA, nullptr, 5, 2, 6);
    reduce_finalize<<<1, 512>>>(6, invH, GPARTS);
    gemm_mma<<<grid, 256>>>(stA, HPAD, sw4, HPAD, b4, HPAD, HDIM,
                            nullptr, h4, 6, 3, -1);

    fc_out<<<(B_ROWS * 32) / 256, 256>>>(h4, W5, b5, out);

    (void)in_sizes; (void)n_in; (void)out_size;
}